// round 1
// baseline (speedup 1.0000x reference)
#include <cuda_runtime.h>
#include <cstdint>

#define BB 4
#define SS 2048
#define DD 1024
#define HH 16
#define DK 64
#define M_TOT (BB*SS)   // 8192

// Scratch (allocation-free rule: __device__ globals)
__device__ float g_Q[BB*HH*SS*DK];      // [B,H,S,DK] 32MB
__device__ float g_K[BB*HH*SS*DK];
__device__ float g_V[BB*HH*SS*DK];
__device__ float g_Ct[(size_t)M_TOT*DD]; // concat heads [B*S, H*DV] 32MB

// ---------------------------------------------------------------------------
// QKV projection GEMM: for z in {Q,K,V}: C[m, h*64+k] = sum_d x[m,d] * W[h,d,k]
// Output written directly in [B,H,S,DK] layout for the attention kernel.
// Tile: 64x64, BK=16, 256 threads, 4x4 per thread.
// ---------------------------------------------------------------------------
__global__ __launch_bounds__(256, 2) void qkv_gemm(
    const float* __restrict__ x,
    const float* __restrict__ Wq,
    const float* __restrict__ Wk,
    const float* __restrict__ Wv)
{
    __shared__ float As[16*64];   // As[kc][m] (transposed)
    __shared__ float Bs[16*64];   // Bs[kc][n]

    const int bm = blockIdx.x;        // 0..127
    const int h  = blockIdx.y;        // 0..15 (head == N-tile)
    const int z  = blockIdx.z;        // 0,1,2

    const float* W = (z == 0) ? Wq : (z == 1) ? Wk : Wv;
    float* Cout    = (z == 0) ? g_Q : (z == 1) ? g_K : g_V;
    const float* Wh = W + (size_t)h * DD * DK;   // head slab [D][64]

    const int m0  = bm * 64;
    const int tid = threadIdx.x;
    const int tx  = tid & 15;
    const int ty  = tid >> 4;

    // A-tile loader: row = tid/4 (0..63), 4 consecutive k's
    const int ar = tid >> 2;
    const int ac = (tid & 3) * 4;
    // B-tile loader: k-row = tid/16 (0..15), 4 consecutive n's
    const int br = tid >> 4;
    const int bc = (tid & 15) * 4;

    float acc[4][4];
    #pragma unroll
    for (int i = 0; i < 4; ++i)
        #pragma unroll
        for (int j = 0; j < 4; ++j) acc[i][j] = 0.f;

    const float4* As4 = reinterpret_cast<const float4*>(As);
    const float4* Bs4 = reinterpret_cast<const float4*>(Bs);

    for (int k0 = 0; k0 < DD; k0 += 16) {
        float4 av = *reinterpret_cast<const float4*>(&x[(size_t)(m0 + ar) * DD + k0 + ac]);
        As[(ac + 0) * 64 + ar] = av.x;
        As[(ac + 1) * 64 + ar] = av.y;
        As[(ac + 2) * 64 + ar] = av.z;
        As[(ac + 3) * 64 + ar] = av.w;
        *reinterpret_cast<float4*>(&Bs[br * 64 + bc]) =
            *reinterpret_cast<const float4*>(&Wh[(size_t)(k0 + br) * DK + bc]);
        __syncthreads();

        #pragma unroll
        for (int kk = 0; kk < 16; ++kk) {
            float4 a4 = As4[kk * 16 + ty];
            float4 b4 = Bs4[kk * 16 + tx];
            float am[4] = {a4.x, a4.y, a4.z, a4.w};
            float bn[4] = {b4.x, b4.y, b4.z, b4.w};
            #pragma unroll
            for (int i = 0; i < 4; ++i)
                #pragma unroll
                for (int j = 0; j < 4; ++j)
                    acc[i][j] += am[i] * bn[j];
        }
        __syncthreads();
    }

    // Epilogue: write [B,H,S,DK]
    #pragma unroll
    for (int i = 0; i < 4; ++i) {
        const int m = m0 + ty * 4 + i;
        const int b = m >> 11;
        const int s = m & 2047;
        float4 v = make_float4(acc[i][0], acc[i][1], acc[i][2], acc[i][3]);
        *reinterpret_cast<float4*>(
            &Cout[(((size_t)(b * HH + h)) * SS + s) * DK + tx * 4]) = v;
    }
}

// ---------------------------------------------------------------------------
// Flash attention: one block = one (b,h) and 64 query rows. 256 threads,
// 4 threads per query row (each owns 16 key-cols of S-tile & 16 V-cols).
// q row kept in registers; K smem XOR-swizzled for conflict-free QK^T reads.
// ---------------------------------------------------------------------------
__global__ __launch_bounds__(256, 1) void flash_attn()
{
    __shared__ float Ks[64 * 64];
    __shared__ float Vs[64 * 64];

    const int q0 = blockIdx.x * 64;
    const int bh = blockIdx.y;               // b*H + h
    const float* Qp = g_Q + (size_t)bh * SS * DK;
    const float* Kp = g_K + (size_t)bh * SS * DK;
    const float* Vp = g_V + (size_t)bh * SS * DK;

    const int tid  = threadIdx.x;
    const int r    = tid >> 2;   // query row within tile (0..63)
    const int qd   = tid & 3;    // quarter (key/value column group)
    const int lane = tid & 31;

    float4* Ks4 = reinterpret_cast<float4*>(Ks);
    float4* Vs4 = reinterpret_cast<float4*>(Vs);

    // ---- Preload Q tile into smem (swizzled), then to registers ----
    {
        const float4* src = reinterpret_cast<const float4*>(Qp + (size_t)q0 * DK);
        for (int i = tid; i < 64 * 16; i += 256) {
            int j = i >> 4, d4 = i & 15;
            Ks4[j * 16 + (d4 ^ ((j >> 4) & 3))] = src[i];
        }
    }
    __syncthreads();

    float q[64];
    #pragma unroll
    for (int d4 = 0; d4 < 16; ++d4) {
        float4 v = Ks4[r * 16 + (d4 ^ ((r >> 4) & 3))];
        q[d4 * 4 + 0] = v.x; q[d4 * 4 + 1] = v.y;
        q[d4 * 4 + 2] = v.z; q[d4 * 4 + 3] = v.w;
    }
    __syncthreads();

    float o[16];
    #pragma unroll
    for (int v = 0; v < 16; ++v) o[v] = 0.f;
    float mrow = -1e30f, lrow = 0.f;
    const float scale = 0.125f;  // 1/sqrt(64)

    for (int kt = 0; kt < SS; kt += 64) {
        // ---- cooperative load of K/V tiles (swizzled) ----
        {
            const float4* ksrc = reinterpret_cast<const float4*>(Kp + (size_t)kt * DK);
            const float4* vsrc = reinterpret_cast<const float4*>(Vp + (size_t)kt * DK);
            for (int i = tid; i < 64 * 16; i += 256) {
                int j = i >> 4, d4 = i & 15;
                int sw = j * 16 + (d4 ^ ((j >> 4) & 3));
                Ks4[sw] = ksrc[i];
                Vs4[sw] = vsrc[i];
            }
        }
        __syncthreads();

        // ---- scores for my 16 key-columns: s[jj] = q . K[qd*16+jj] ----
        float s[16];
        #pragma unroll
        for (int jj = 0; jj < 16; ++jj) {
            const int j = qd * 16 + jj;
            float acc = 0.f;
            #pragma unroll
            for (int d4 = 0; d4 < 16; ++d4) {
                float4 kv = Ks4[j * 16 + (d4 ^ qd)];
                acc += q[d4 * 4 + 0] * kv.x;
                acc += q[d4 * 4 + 1] * kv.y;
                acc += q[d4 * 4 + 2] * kv.z;
                acc += q[d4 * 4 + 3] * kv.w;
            }
            s[jj] = acc * scale;
        }

        // ---- online softmax (row group = 4 adjacent lanes) ----
        float mt = s[0];
        #pragma unroll
        for (int jj = 1; jj < 16; ++jj) mt = fmaxf(mt, s[jj]);
        mt = fmaxf(mt, __shfl_xor_sync(0xffffffffu, mt, 1));
        mt = fmaxf(mt, __shfl_xor_sync(0xffffffffu, mt, 2));
        const float mnew = fmaxf(mrow, mt);
        const float corr = __expf(mrow - mnew);
        float lsum = 0.f;
        #pragma unroll
        for (int jj = 0; jj < 16; ++jj) {
            s[jj] = __expf(s[jj] - mnew);
            lsum += s[jj];
        }
        lsum += __shfl_xor_sync(0xffffffffu, lsum, 1);
        lsum += __shfl_xor_sync(0xffffffffu, lsum, 2);
        lrow = lrow * corr + lsum;
        mrow = mnew;
        #pragma unroll
        for (int v = 0; v < 16; ++v) o[v] *= corr;

        // ---- o += P @ V  (p_j fetched via shfl from row-group owner) ----
        #pragma unroll
        for (int jq = 0; jq < 4; ++jq) {
            #pragma unroll
            for (int jj = 0; jj < 16; ++jj) {
                const float pj = __shfl_sync(0xffffffffu, s[jj], (lane & ~3) | jq);
                const int j = jq * 16 + jj;
                const int c = (j >> 4) & 3;
                #pragma unroll
                for (int vg = 0; vg < 4; ++vg) {
                    float4 vv = Vs4[j * 16 + ((qd * 4 + vg) ^ c)];
                    o[vg * 4 + 0] += pj * vv.x;
                    o[vg * 4 + 1] += pj * vv.y;
                    o[vg * 4 + 2] += pj * vv.z;
                    o[vg * 4 + 3] += pj * vv.w;
                }
            }
        }
        __syncthreads();
    }

    // ---- epilogue: normalize and write concat layout [B*S, H*64] ----
    const float inv = 1.f / lrow;
    const int b = bh / HH, h = bh % HH;
    const size_t m = (size_t)b * SS + q0 + r;
    float* dst = &g_Ct[m * DD + h * 64 + qd * 16];
    #pragma unroll
    for (int vg = 0; vg < 4; ++vg) {
        float4 v = make_float4(o[vg * 4 + 0] * inv, o[vg * 4 + 1] * inv,
                               o[vg * 4 + 2] * inv, o[vg * 4 + 3] * inv);
        *reinterpret_cast<float4*>(dst + vg * 4) = v;
    }
}

// ---------------------------------------------------------------------------
// Output projection GEMM: out[m,n] = sum_k g_Ct[m,k] * Wo[k,n]
// ---------------------------------------------------------------------------
__global__ __launch_bounds__(256, 2) void out_gemm(
    const float* __restrict__ Wo, float* __restrict__ out)
{
    __shared__ float As[16*64];
    __shared__ float Bs[16*64];

    const int bm = blockIdx.x;    // 0..127
    const int bn = blockIdx.y;    // 0..15
    const int m0 = bm * 64;
    const int n0 = bn * 64;
    const int tid = threadIdx.x;
    const int tx = tid & 15;
    const int ty = tid >> 4;
    const int ar = tid >> 2;
    const int ac = (tid & 3) * 4;
    const int br = tid >> 4;
    const int bc = (tid & 15) * 4;

    float acc[4][4];
    #pragma unroll
    for (int i = 0; i < 4; ++i)
        #pragma unroll
        for (int j = 0; j < 4; ++j) acc[i][j] = 0.f;

    const float4* As4 = reinterpret_cast<const float4*>(As);
    const float4* Bs4 = reinterpret_cast<const float4*>(Bs);

    for (int k0 = 0; k0 < DD; k0 += 16) {
        float4 av = *reinterpret_cast<const float4*>(&g_Ct[(size_t)(m0 + ar) * DD + k0 + ac]);
        As[(ac + 0) * 64 + ar] = av.x;
        As[(ac + 1) * 64 + ar] = av.y;
        As[(ac + 2) * 64 + ar] = av.z;
        As[(ac + 3) * 64 + ar] = av.w;
        *reinterpret_cast<float4*>(&Bs[br * 64 + bc]) =
            *reinterpret_cast<const float4*>(&Wo[(size_t)(k0 + br) * DD + n0 + bc]);
        __syncthreads();

        #pragma unroll
        for (int kk = 0; kk < 16; ++kk) {
            float4 a4 = As4[kk * 16 + ty];
            float4 b4 = Bs4[kk * 16 + tx];
            float am[4] = {a4.x, a4.y, a4.z, a4.w};
            float bn_[4] = {b4.x, b4.y, b4.z, b4.w};
            #pragma unroll
            for (int i = 0; i < 4; ++i)
                #pragma unroll
                for (int j = 0; j < 4; ++j)
                    acc[i][j] += am[i] * bn_[j];
        }
        __syncthreads();
    }

    #pragma unroll
    for (int i = 0; i < 4; ++i) {
        const int m = m0 + ty * 4 + i;
        float4 v = make_float4(acc[i][0], acc[i][1], acc[i][2], acc[i][3]);
        *reinterpret_cast<float4*>(&out[(size_t)m * DD + n0 + tx * 4]) = v;
    }
}

extern "C" void kernel_launch(void* const* d_in, const int* in_sizes, int n_in,
                              void* d_out, int out_size)
{
    const float* x  = (const float*)d_in[0];
    const float* Wq = (const float*)d_in[1];
    const float* Wk = (const float*)d_in[2];
    const float* Wv = (const float*)d_in[3];
    const float* Wo = (const float*)d_in[4];
    float* out = (float*)d_out;

    (void)in_sizes; (void)n_in; (void)out_size;

    qkv_gemm<<<dim3(M_TOT / 64, HH, 3), 256>>>(x, Wq, Wk, Wv);
    flash_attn<<<dim3(SS / 64, BB * HH), 256>>>();
    out_gemm<<<dim3(M_TOT / 64, DD / 64), 256>>>(Wo, out);
}

// round 2
// speedup vs baseline: 4.3724x; 4.3724x over previous
#include <cuda_runtime.h>
#include <cstdint>

#define BB 4
#define SS 2048
#define DD 1024
#define HH 16
#define DK 64
#define M_TOT (BB*SS)   // 8192

// Scratch (allocation-free rule: __device__ globals)
__device__ float g_Q[BB*HH*SS*DK];
__device__ float g_K[BB*HH*SS*DK];
__device__ float g_V[BB*HH*SS*DK];
__device__ float g_Ct[(size_t)M_TOT*DD];

// ---------------------------------------------------------------------------
// tf32 helpers
// ---------------------------------------------------------------------------
__device__ __forceinline__ uint32_t f2tf32(float f) {
    uint32_t r;
    asm("cvt.rna.tf32.f32 %0, %1;" : "=r"(r) : "f"(f));
    return r;
}

__device__ __forceinline__ void mma_tf32(float* c, const uint32_t* a, const uint32_t* b) {
    asm volatile(
        "mma.sync.aligned.m16n8k8.row.col.f32.tf32.tf32.f32 "
        "{%0,%1,%2,%3}, {%4,%5,%6,%7}, {%8,%9}, {%0,%1,%2,%3};"
        : "+f"(c[0]), "+f"(c[1]), "+f"(c[2]), "+f"(c[3])
        : "r"(a[0]), "r"(a[1]), "r"(a[2]), "r"(a[3]), "r"(b[0]), "r"(b[1]));
}

// ---------------------------------------------------------------------------
// QKV projection: C[m, h, k] = sum_d x[m,d] * W[h,d,k], z selects Q/K/V.
// Block tile 128x64, BK=16, 256 threads (8 warps, 4x2), warp tile 32x32.
// ---------------------------------------------------------------------------
#define APITCH 20   // 16 + 4 pad: conflict-free A-frag reads
#define BPITCH 72   // 64 + 8 pad: conflict-free B-frag reads

__global__ __launch_bounds__(256) void qkv_gemm_t(
    const float* __restrict__ x,
    const float* __restrict__ Wq,
    const float* __restrict__ Wk,
    const float* __restrict__ Wv)
{
    __shared__ uint32_t As[128 * APITCH];
    __shared__ uint32_t Bs[16 * BPITCH];

    const int m0 = blockIdx.x * 128;
    const int h  = blockIdx.y;
    const int z  = blockIdx.z;
    const float* W = (z == 0) ? Wq : (z == 1) ? Wk : Wv;
    float* Cout    = (z == 0) ? g_Q : (z == 1) ? g_K : g_V;
    const float* Wh = W + (size_t)h * DD * DK;

    const int tid  = threadIdx.x;
    const int warp = tid >> 5;
    const int lane = tid & 31;
    const int g    = lane >> 2;
    const int tig  = lane & 3;
    const int wm   = (warp & 3) * 32;
    const int wn   = (warp >> 2) * 32;

    // A loader: row = tid>>1 (0..127), 8 cols starting at (tid&1)*8
    const int ar = tid >> 1;
    const int ac = (tid & 1) * 8;
    // B loader: row k = tid>>4 (0..15), 4 cols at (tid&15)*4
    const int bk = tid >> 4;
    const int bn = (tid & 15) * 4;

    float acc[2][4][4];
    #pragma unroll
    for (int i = 0; i < 2; ++i)
        #pragma unroll
        for (int j = 0; j < 4; ++j)
            #pragma unroll
            for (int l = 0; l < 4; ++l) acc[i][j][l] = 0.f;

    float4 av0, av1, bv;
    av0 = *reinterpret_cast<const float4*>(&x[(size_t)(m0 + ar) * DD + ac]);
    av1 = *reinterpret_cast<const float4*>(&x[(size_t)(m0 + ar) * DD + ac + 4]);
    bv  = *reinterpret_cast<const float4*>(&Wh[(size_t)bk * DK + bn]);

    for (int k0 = 0; k0 < DD; k0 += 16) {
        As[ar * APITCH + ac + 0] = f2tf32(av0.x);
        As[ar * APITCH + ac + 1] = f2tf32(av0.y);
        As[ar * APITCH + ac + 2] = f2tf32(av0.z);
        As[ar * APITCH + ac + 3] = f2tf32(av0.w);
        As[ar * APITCH + ac + 4] = f2tf32(av1.x);
        As[ar * APITCH + ac + 5] = f2tf32(av1.y);
        As[ar * APITCH + ac + 6] = f2tf32(av1.z);
        As[ar * APITCH + ac + 7] = f2tf32(av1.w);
        Bs[bk * BPITCH + bn + 0] = f2tf32(bv.x);
        Bs[bk * BPITCH + bn + 1] = f2tf32(bv.y);
        Bs[bk * BPITCH + bn + 2] = f2tf32(bv.z);
        Bs[bk * BPITCH + bn + 3] = f2tf32(bv.w);
        __syncthreads();

        if (k0 + 16 < DD) {
            av0 = *reinterpret_cast<const float4*>(&x[(size_t)(m0 + ar) * DD + k0 + 16 + ac]);
            av1 = *reinterpret_cast<const float4*>(&x[(size_t)(m0 + ar) * DD + k0 + 16 + ac + 4]);
            bv  = *reinterpret_cast<const float4*>(&Wh[(size_t)(k0 + 16 + bk) * DK + bn]);
        }

        #pragma unroll
        for (int kc = 0; kc < 2; ++kc) {
            uint32_t af[2][4];
            #pragma unroll
            for (int mt = 0; mt < 2; ++mt) {
                const int rb = wm + mt * 16;
                af[mt][0] = As[(rb + g)     * APITCH + kc * 8 + tig];
                af[mt][1] = As[(rb + g + 8) * APITCH + kc * 8 + tig];
                af[mt][2] = As[(rb + g)     * APITCH + kc * 8 + tig + 4];
                af[mt][3] = As[(rb + g + 8) * APITCH + kc * 8 + tig + 4];
            }
            uint32_t bf[4][2];
            #pragma unroll
            for (int nt = 0; nt < 4; ++nt) {
                bf[nt][0] = Bs[(kc * 8 + tig)     * BPITCH + wn + nt * 8 + g];
                bf[nt][1] = Bs[(kc * 8 + tig + 4) * BPITCH + wn + nt * 8 + g];
            }
            #pragma unroll
            for (int mt = 0; mt < 2; ++mt)
                #pragma unroll
                for (int nt = 0; nt < 4; ++nt)
                    mma_tf32(acc[mt][nt], af[mt], bf[nt]);
        }
        __syncthreads();
    }

    // Epilogue: write [B,H,S,64]
    #pragma unroll
    for (int mt = 0; mt < 2; ++mt) {
        #pragma unroll
        for (int nt = 0; nt < 4; ++nt) {
            const int col = wn + nt * 8 + 2 * tig;   // 0..63, even
            #pragma unroll
            for (int rh = 0; rh < 2; ++rh) {
                const int m = m0 + wm + mt * 16 + g + rh * 8;
                const int b = m >> 11;
                const int s = m & 2047;
                float2 v = make_float2(acc[mt][nt][rh * 2], acc[mt][nt][rh * 2 + 1]);
                *reinterpret_cast<float2*>(
                    &Cout[(((size_t)(b * HH + h)) * SS + s) * DK + col]) = v;
            }
        }
    }
}

// ---------------------------------------------------------------------------
// Output projection: out[m,n] = sum_k g_Ct[m,k] * Wo[k,n]
// ---------------------------------------------------------------------------
__global__ __launch_bounds__(256) void out_gemm_t(
    const float* __restrict__ Wo, float* __restrict__ out)
{
    __shared__ uint32_t As[128 * APITCH];
    __shared__ uint32_t Bs[16 * BPITCH];

    const int m0 = blockIdx.x * 128;
    const int n0 = blockIdx.y * 64;

    const int tid  = threadIdx.x;
    const int warp = tid >> 5;
    const int lane = tid & 31;
    const int g    = lane >> 2;
    const int tig  = lane & 3;
    const int wm   = (warp & 3) * 32;
    const int wn   = (warp >> 2) * 32;

    const int ar = tid >> 1;
    const int ac = (tid & 1) * 8;
    const int bk = tid >> 4;
    const int bn = (tid & 15) * 4;

    float acc[2][4][4];
    #pragma unroll
    for (int i = 0; i < 2; ++i)
        #pragma unroll
        for (int j = 0; j < 4; ++j)
            #pragma unroll
            for (int l = 0; l < 4; ++l) acc[i][j][l] = 0.f;

    float4 av0, av1, bv;
    av0 = *reinterpret_cast<const float4*>(&g_Ct[(size_t)(m0 + ar) * DD + ac]);
    av1 = *reinterpret_cast<const float4*>(&g_Ct[(size_t)(m0 + ar) * DD + ac + 4]);
    bv  = *reinterpret_cast<const float4*>(&Wo[(size_t)bk * DD + n0 + bn]);

    for (int k0 = 0; k0 < DD; k0 += 16) {
        As[ar * APITCH + ac + 0] = f2tf32(av0.x);
        As[ar * APITCH + ac + 1] = f2tf32(av0.y);
        As[ar * APITCH + ac + 2] = f2tf32(av0.z);
        As[ar * APITCH + ac + 3] = f2tf32(av0.w);
        As[ar * APITCH + ac + 4] = f2tf32(av1.x);
        As[ar * APITCH + ac + 5] = f2tf32(av1.y);
        As[ar * APITCH + ac + 6] = f2tf32(av1.z);
        As[ar * APITCH + ac + 7] = f2tf32(av1.w);
        Bs[bk * BPITCH + bn + 0] = f2tf32(bv.x);
        Bs[bk * BPITCH + bn + 1] = f2tf32(bv.y);
        Bs[bk * BPITCH + bn + 2] = f2tf32(bv.z);
        Bs[bk * BPITCH + bn + 3] = f2tf32(bv.w);
        __syncthreads();

        if (k0 + 16 < DD) {
            av0 = *reinterpret_cast<const float4*>(&g_Ct[(size_t)(m0 + ar) * DD + k0 + 16 + ac]);
            av1 = *reinterpret_cast<const float4*>(&g_Ct[(size_t)(m0 + ar) * DD + k0 + 16 + ac + 4]);
            bv  = *reinterpret_cast<const float4*>(&Wo[(size_t)(k0 + 16 + bk) * DD + n0 + bn]);
        }

        #pragma unroll
        for (int kc = 0; kc < 2; ++kc) {
            uint32_t af[2][4];
            #pragma unroll
            for (int mt = 0; mt < 2; ++mt) {
                const int rb = wm + mt * 16;
                af[mt][0] = As[(rb + g)     * APITCH + kc * 8 + tig];
                af[mt][1] = As[(rb + g + 8) * APITCH + kc * 8 + tig];
                af[mt][2] = As[(rb + g)     * APITCH + kc * 8 + tig + 4];
                af[mt][3] = As[(rb + g + 8) * APITCH + kc * 8 + tig + 4];
            }
            uint32_t bf[4][2];
            #pragma unroll
            for (int nt = 0; nt < 4; ++nt) {
                bf[nt][0] = Bs[(kc * 8 + tig)     * BPITCH + wn + nt * 8 + g];
                bf[nt][1] = Bs[(kc * 8 + tig + 4) * BPITCH + wn + nt * 8 + g];
            }
            #pragma unroll
            for (int mt = 0; mt < 2; ++mt)
                #pragma unroll
                for (int nt = 0; nt < 4; ++nt)
                    mma_tf32(acc[mt][nt], af[mt], bf[nt]);
        }
        __syncthreads();
    }

    #pragma unroll
    for (int mt = 0; mt < 2; ++mt) {
        #pragma unroll
        for (int nt = 0; nt < 4; ++nt) {
            const int col = n0 + wn + nt * 8 + 2 * tig;
            #pragma unroll
            for (int rh = 0; rh < 2; ++rh) {
                const int m = m0 + wm + mt * 16 + g + rh * 8;
                float2 v = make_float2(acc[mt][nt][rh * 2], acc[mt][nt][rh * 2 + 1]);
                *reinterpret_cast<float2*>(&out[(size_t)m * DD + col]) = v;
            }
        }
    }
}

// ---------------------------------------------------------------------------
// Flash attention (tf32 mma): block = 64 q-rows of one (b,h). 4 warps,
// warp owns 16 q-rows. K tile and P tile share one smem buffer (KP).
// Q is pre-scaled by 1/8 and kept in registers as mma A fragments.
// ---------------------------------------------------------------------------
__global__ __launch_bounds__(128) void flash_attn_t()
{
    __shared__ uint32_t KP[64 * BPITCH];   // K tile, then P tile (also Q staging)
    __shared__ uint32_t Vs[64 * BPITCH];

    const int q0 = blockIdx.x * 64;
    const int bh = blockIdx.y;
    const float* Qp = g_Q + (size_t)bh * SS * DK;
    const float* Kp = g_K + (size_t)bh * SS * DK;
    const float* Vp = g_V + (size_t)bh * SS * DK;

    const int tid  = threadIdx.x;
    const int w    = tid >> 5;
    const int lane = tid & 31;
    const int g    = lane >> 2;
    const int tig  = lane & 3;
    const int wr   = w * 16;

    // tile loader mapping: row = tid>>1 (0..63), 32 cols at (tid&1)*32
    const int lr = tid >> 1;
    const int lc = (tid & 1) * 32;

    // ---- stage Q (scaled by 1/8, tf32) into KP, then load A-fragments ----
    {
        const float4* src = reinterpret_cast<const float4*>(Qp + (size_t)(q0 + lr) * DK + lc);
        #pragma unroll
        for (int i = 0; i < 8; ++i) {
            float4 v = src[i];
            uint32_t* d = &KP[lr * BPITCH + lc + i * 4];
            d[0] = f2tf32(0.125f * v.x);
            d[1] = f2tf32(0.125f * v.y);
            d[2] = f2tf32(0.125f * v.z);
            d[3] = f2tf32(0.125f * v.w);
        }
    }
    __syncthreads();

    uint32_t qf[8][4];
    #pragma unroll
    for (int kc = 0; kc < 8; ++kc) {
        qf[kc][0] = KP[(wr + g)     * BPITCH + kc * 8 + tig];
        qf[kc][1] = KP[(wr + g + 8) * BPITCH + kc * 8 + tig];
        qf[kc][2] = KP[(wr + g)     * BPITCH + kc * 8 + tig + 4];
        qf[kc][3] = KP[(wr + g + 8) * BPITCH + kc * 8 + tig + 4];
    }

    float of[8][4];
    #pragma unroll
    for (int nt = 0; nt < 8; ++nt)
        #pragma unroll
        for (int i = 0; i < 4; ++i) of[nt][i] = 0.f;
    float mA = -1e30f, mB = -1e30f, lA = 0.f, lB = 0.f;

    for (int kt = 0; kt < SS; kt += 64) {
        __syncthreads();   // prior reads of KP (Q frags / P) and Vs complete

        // ---- load K and V tiles (tf32) ----
        {
            const float4* ks = reinterpret_cast<const float4*>(Kp + (size_t)(kt + lr) * DK + lc);
            const float4* vs = reinterpret_cast<const float4*>(Vp + (size_t)(kt + lr) * DK + lc);
            #pragma unroll
            for (int i = 0; i < 8; ++i) {
                float4 kv = ks[i];
                float4 vv = vs[i];
                uint32_t* dk_ = &KP[lr * BPITCH + lc + i * 4];
                uint32_t* dv_ = &Vs[lr * BPITCH + lc + i * 4];
                dk_[0] = f2tf32(kv.x); dk_[1] = f2tf32(kv.y);
                dk_[2] = f2tf32(kv.z); dk_[3] = f2tf32(kv.w);
                dv_[0] = f2tf32(vv.x); dv_[1] = f2tf32(vv.y);
                dv_[2] = f2tf32(vv.z); dv_[3] = f2tf32(vv.w);
            }
        }
        __syncthreads();

        // ---- S = Q K^T (scaled) ----
        float sf[8][4];
        #pragma unroll
        for (int nt = 0; nt < 8; ++nt) {
            float c[4] = {0.f, 0.f, 0.f, 0.f};
            #pragma unroll
            for (int kc = 0; kc < 8; ++kc) {
                uint32_t bf[2];
                bf[0] = KP[(nt * 8 + g) * BPITCH + kc * 8 + tig];
                bf[1] = KP[(nt * 8 + g) * BPITCH + kc * 8 + tig + 4];
                mma_tf32(c, qf[kc], bf);
            }
            sf[nt][0] = c[0]; sf[nt][1] = c[1]; sf[nt][2] = c[2]; sf[nt][3] = c[3];
        }

        // ---- online softmax (rows g and g+8 of this warp's 16) ----
        float mtA = sf[0][0], mtB = sf[0][2];
        #pragma unroll
        for (int nt = 0; nt < 8; ++nt) {
            mtA = fmaxf(mtA, fmaxf(sf[nt][0], sf[nt][1]));
            mtB = fmaxf(mtB, fmaxf(sf[nt][2], sf[nt][3]));
        }
        mtA = fmaxf(mtA, __shfl_xor_sync(0xffffffffu, mtA, 1));
        mtA = fmaxf(mtA, __shfl_xor_sync(0xffffffffu, mtA, 2));
        mtB = fmaxf(mtB, __shfl_xor_sync(0xffffffffu, mtB, 1));
        mtB = fmaxf(mtB, __shfl_xor_sync(0xffffffffu, mtB, 2));

        const float mnA = fmaxf(mA, mtA);
        const float mnB = fmaxf(mB, mtB);
        const float cA = __expf(mA - mnA);
        const float cB = __expf(mB - mnB);

        float sumA = 0.f, sumB = 0.f;
        #pragma unroll
        for (int nt = 0; nt < 8; ++nt) {
            sf[nt][0] = __expf(sf[nt][0] - mnA);
            sf[nt][1] = __expf(sf[nt][1] - mnA);
            sf[nt][2] = __expf(sf[nt][2] - mnB);
            sf[nt][3] = __expf(sf[nt][3] - mnB);
            sumA += sf[nt][0] + sf[nt][1];
            sumB += sf[nt][2] + sf[nt][3];
        }
        sumA += __shfl_xor_sync(0xffffffffu, sumA, 1);
        sumA += __shfl_xor_sync(0xffffffffu, sumA, 2);
        sumB += __shfl_xor_sync(0xffffffffu, sumB, 1);
        sumB += __shfl_xor_sync(0xffffffffu, sumB, 2);

        lA = lA * cA + sumA; mA = mnA;
        lB = lB * cB + sumB; mB = mnB;
        #pragma unroll
        for (int nt = 0; nt < 8; ++nt) {
            of[nt][0] *= cA; of[nt][1] *= cA;
            of[nt][2] *= cB; of[nt][3] *= cB;
        }

        __syncthreads();   // all warps done reading K tile from KP

        // ---- store P (tf32) into KP, warp-local rows ----
        #pragma unroll
        for (int nt = 0; nt < 8; ++nt) {
            uint2 p0, p1;
            p0.x = f2tf32(sf[nt][0]); p0.y = f2tf32(sf[nt][1]);
            p1.x = f2tf32(sf[nt][2]); p1.y = f2tf32(sf[nt][3]);
            *reinterpret_cast<uint2*>(&KP[(wr + g)     * BPITCH + nt * 8 + 2 * tig]) = p0;
            *reinterpret_cast<uint2*>(&KP[(wr + g + 8) * BPITCH + nt * 8 + 2 * tig]) = p1;
        }
        __syncwarp();

        // ---- O += P V ----
        uint32_t pf[8][4];
        #pragma unroll
        for (int kc = 0; kc < 8; ++kc) {
            pf[kc][0] = KP[(wr + g)     * BPITCH + kc * 8 + tig];
            pf[kc][1] = KP[(wr + g + 8) * BPITCH + kc * 8 + tig];
            pf[kc][2] = KP[(wr + g)     * BPITCH + kc * 8 + tig + 4];
            pf[kc][3] = KP[(wr + g + 8) * BPITCH + kc * 8 + tig + 4];
        }
        #pragma unroll
        for (int nt = 0; nt < 8; ++nt) {
            #pragma unroll
            for (int kc = 0; kc < 8; ++kc) {
                uint32_t bf[2];
                bf[0] = Vs[(kc * 8 + tig)     * BPITCH + nt * 8 + g];
                bf[1] = Vs[(kc * 8 + tig + 4) * BPITCH + nt * 8 + g];
                mma_tf32(of[nt], pf[kc], bf);
            }
        }
    }

    // ---- epilogue ----
    const float invA = 1.f / lA;
    const float invB = 1.f / lB;
    const int b = bh >> 4, h = bh & 15;
    const size_t rowA = (size_t)b * SS + q0 + wr + g;
    const size_t rowB = rowA + 8;
    #pragma unroll
    for (int nt = 0; nt < 8; ++nt) {
        const int col = h * 64 + nt * 8 + 2 * tig;
        *reinterpret_cast<float2*>(&g_Ct[rowA * DD + col]) =
            make_float2(of[nt][0] * invA, of[nt][1] * invA);
        *reinterpret_cast<float2*>(&g_Ct[rowB * DD + col]) =
            make_float2(of[nt][2] * invB, of[nt][3] * invB);
    }
}

extern "C" void kernel_launch(void* const* d_in, const int* in_sizes, int n_in,
                              void* d_out, int out_size)
{
    const float* x  = (const float*)d_in[0];
    const float* Wq = (const float*)d_in[1];
    const float* Wk = (const float*)d_in[2];
    const float* Wv = (const float*)d_in[3];
    const float* Wo = (const float*)d_in[4];
    float* out = (float*)d_out;

    (void)in_sizes; (void)n_in; (void)out_size;

    qkv_gemm_t<<<dim3(M_TOT / 128, HH, 3), 256>>>(x, Wq, Wk, Wv);
    flash_attn_t<<<dim3(SS / 64, BB * HH), 128>>>();
    out_gemm_t<<<dim3(M_TOT / 128, DD / 64), 256>>>(Wo, out);
}